// round 15
// baseline (speedup 1.0000x reference)
#include <cuda_runtime.h>

#define NEG_INF -3.402823466e38f
#define POS_INF 3.402823466e38f

// ------------ device scratch ------------
__device__ float g_distm[4UL*4096*4096];
__device__ float g_distp[4UL*1024*4096];
__device__ float g_xT[4*4096*9];
__device__ float g_coord[4*4096*3];
__device__ int   g_idx[4*4096*20];
__device__ int   g_idxp1[4*1024*20];
__device__ int   g_idxp2[4*256*20];
__device__ int   g_idxp3[4*64*20];
__device__ float g_cc[4*4096*64];
__device__ float g_h[4*4096*64];
__device__ float g_x0[4*4096*64];
__device__ float g_h1[4*1024*64];
__device__ float g_x1[4*1024*64];
__device__ float g_x1r[4*1024*64];
__device__ float g_n1f[4*1024*64];
__device__ float g_h2[4*256*64];
__device__ float g_x2[4*256*64];
__device__ float g_x2r[4*256*64];
__device__ float g_n2f[4*256*64];
__device__ float g_h3[4*64*64];
__device__ float g_x3[4*64*64];
__device__ float g_x3r[4*64*64];
__device__ float g_n3f[4*64*64];
__device__ float g_xt[4*4*1024];
__device__ float g_gv[4*1024];
__device__ float g_b13[4*256];
__device__ float g_part[4*1024*64];
__device__ float g_dec0[4UL*4096*256];
__device__ float g_dec1[4UL*4096*256];
__device__ int   g_uidxA[4*256];
__device__ int   g_uidxB[4*1024];
__device__ int   g_uidxC[4*4096];

__device__ __forceinline__ float lrelu(float v){ return v > 0.f ? v : 0.2f*v; }

// ------------ prep: transpose x, coords ------------
__global__ void __launch_bounds__(256) prep_kernel(const float* __restrict__ x){
    int n = blockIdx.x*256 + threadIdx.x, b = blockIdx.y;
    if (n >= 4096) return;
    const float* xb = x + (size_t)b*9*4096;
    float v[9];
#pragma unroll
    for (int c = 0; c < 9; c++) v[c] = xb[(size_t)c*4096 + n];
    float* r = g_xT + ((size_t)b*4096 + n)*9;
#pragma unroll
    for (int c = 0; c < 9; c++) r[c] = v[c];
    float* cr = g_coord + ((size_t)b*4096 + n)*3;
    cr[0]=v[0]; cr[1]=v[1]; cr[2]=v[2];
}

// node1/2/3 outputs (slices of x)
__global__ void __launch_bounds__(256) nodes_kernel(const float* __restrict__ x, float* __restrict__ o){
    int t = blockIdx.x*256 + threadIdx.x;
    const int T1 = 4*3*1024, T2 = 4*3*256, T3 = 4*3*64;
    if (t < T1) {
        int n = t & 1023, c = (t>>10)%3, b = t/(3*1024);
        o[212992 + t] = x[((size_t)b*9 + c)*4096 + n];
    } else if (t < T1+T2) {
        int u = t-T1; int n = u & 255, c = (u>>8)%3, b = u/(3*256);
        o[212992 + T1 + u] = x[((size_t)b*9 + c)*4096 + n];
    } else if (t < T1+T2+T3) {
        int u = t-T1-T2; int n = u & 63, c = (u>>6)%3, b = u/(3*64);
        o[212992 + T1 + T2 + u] = x[((size_t)b*9 + c)*4096 + n];
    }
}

// ------------ neg dist score 64x64 tile: v = 2<q,r> - |r|^2 ------------
__global__ void __launch_bounds__(256) dist_kernel(
    const float* __restrict__ Q, size_t sQ, const float* __restrict__ R, size_t sR,
    int C, int Qn, int Nr, float* __restrict__ D)
{
    __shared__ float Qs[16][65], Rs[16][65];
    __shared__ float srn[64];
    int b = blockIdx.z, q0 = blockIdx.y*64, r0 = blockIdx.x*64;
    int tx = threadIdx.x, ty = threadIdx.y, t = ty*16 + tx;
    const float* Qb = Q + (size_t)b*sQ;
    const float* Rb = R + (size_t)b*sR;
    float acc[4][4] = {};
    float rnacc = 0.f;
    for (int kt = 0; kt < C; kt += 16) {
        for (int e = t; e < 1024; e += 256) {
            int pl = e >> 4, cc = e & 15, k = kt + cc;
            Qs[cc][pl] = (k < C) ? Qb[(size_t)(q0+pl)*C + k] : 0.f;
            Rs[cc][pl] = (k < C) ? Rb[(size_t)(r0+pl)*C + k] : 0.f;
        }
        __syncthreads();
        if (t < 64) {
#pragma unroll
            for (int cc = 0; cc < 16; cc++) { float v = Rs[cc][t]; rnacc = fmaf(v, v, rnacc); }
        }
#pragma unroll
        for (int cc = 0; cc < 16; cc++) {
            float qv[4], rv[4];
#pragma unroll
            for (int i = 0; i < 4; i++) qv[i] = Qs[cc][ty*4+i];
#pragma unroll
            for (int j = 0; j < 4; j++) rv[j] = Rs[cc][tx*4+j];
#pragma unroll
            for (int i = 0; i < 4; i++)
#pragma unroll
                for (int j = 0; j < 4; j++) acc[i][j] = fmaf(qv[i], rv[j], acc[i][j]);
        }
        __syncthreads();
    }
    if (t < 64) srn[t] = rnacc;
    __syncthreads();
    float4 rn4;
    rn4.x = srn[tx*4]; rn4.y = srn[tx*4+1]; rn4.z = srn[tx*4+2]; rn4.w = srn[tx*4+3];
#pragma unroll
    for (int i = 0; i < 4; i++) {
        int q = q0 + ty*4 + i;
        float4 v;
        v.x = 2.f*acc[i][0] - rn4.x;
        v.y = 2.f*acc[i][1] - rn4.y;
        v.z = 2.f*acc[i][2] - rn4.z;
        v.w = 2.f*acc[i][3] - rn4.w;
        *(float4*)&D[((size_t)b*Qn + q)*Nr + r0 + tx*4] = v;
    }
}

// ------------ neg dist score 128x128 tile / 8x8 ------------
__global__ void __launch_bounds__(256) dist2_kernel(
    const float* __restrict__ Q, size_t sQ, const float* __restrict__ R, size_t sR,
    int C, int QnD, int q0, int Nr, float* __restrict__ D)
{
    __shared__ float Qs[16][132], Rs[16][132];
    __shared__ float srn[128];
    int b = blockIdx.z, qb = blockIdx.y*128, r0 = blockIdx.x*128;
    int t = threadIdx.x;
    int tx = t & 15, ty = t >> 4;
    const float* Qb = Q + (size_t)b*sQ;
    const float* Rb = R + (size_t)b*sR;
    float acc[8][8] = {};
    float rnacc = 0.f;
    for (int kt = 0; kt < C; kt += 16) {
        for (int e = t; e < 2048; e += 256) {
            int row = e >> 4, c = e & 15; int k = kt + c;
            Qs[c][row] = (k < C) ? Qb[(size_t)(q0+qb+row)*C + k] : 0.f;
            Rs[c][row] = (k < C) ? Rb[(size_t)(r0+row)*C + k] : 0.f;
        }
        __syncthreads();
        if (t < 128) {
#pragma unroll
            for (int c = 0; c < 16; c++) { float v = Rs[c][t]; rnacc = fmaf(v, v, rnacc); }
        }
#pragma unroll
        for (int c = 0; c < 16; c++) {
            float qv[8], rv[8];
#pragma unroll
            for (int i = 0; i < 8; i++) qv[i] = Qs[c][ty*8+i];
#pragma unroll
            for (int j = 0; j < 8; j++) rv[j] = Rs[c][tx*8+j];
#pragma unroll
            for (int i = 0; i < 8; i++)
#pragma unroll
                for (int j = 0; j < 8; j++) acc[i][j] = fmaf(qv[i], rv[j], acc[i][j]);
        }
        __syncthreads();
    }
    if (t < 128) srn[t] = rnacc;
    __syncthreads();
    float rn8[8];
#pragma unroll
    for (int j = 0; j < 8; j++) rn8[j] = srn[tx*8 + j];
#pragma unroll
    for (int i = 0; i < 8; i++) {
        int qr = qb + ty*8 + i;
        float4 v0, v1;
        v0.x = 2.f*acc[i][0] - rn8[0];
        v0.y = 2.f*acc[i][1] - rn8[1];
        v0.z = 2.f*acc[i][2] - rn8[2];
        v0.w = 2.f*acc[i][3] - rn8[3];
        v1.x = 2.f*acc[i][4] - rn8[4];
        v1.y = 2.f*acc[i][5] - rn8[5];
        v1.z = 2.f*acc[i][6] - rn8[6];
        v1.w = 2.f*acc[i][7] - rn8[7];
        float* dr = &D[((size_t)b*QnD + qr)*Nr + r0 + tx*8];
        *(float4*)dr = v0;
        *(float4*)(dr + 4) = v1;
    }
}

// ------------ top-k per row: single-pass candidate select with safety check ------------
// phase A keeps per-lane top-4 (v,idx). If no lane dropped a value >= thr (thr = 20th
// of the 128 candidates), the candidate set provably contains the true top-KK and the
// extraction order matches (v desc, idx asc). Otherwise fall back to phase-B rescan.
template <int KK>
__global__ void __launch_bounds__(256) topk_kernel(const float* __restrict__ D, int Mq, int Nr,
                                                   int Qn, int q0, int* __restrict__ out)
{
    const int CAP = 320;
    __shared__ float cv[8][CAP];
    __shared__ int   ci[8][CAP];
    int wp = threadIdx.x >> 5, lane = threadIdx.x & 31;
    int row = blockIdx.x*8 + wp;
    const float4* Dr4 = (const float4*)(D + (size_t)row*Nr);
    int nq = Nr >> 2;
    int iters = (nq + 31) >> 5;

    // phase A: per-lane top-4 with indices (sorted desc; strict > keeps idx-asc on ties)
    float c0=NEG_INF, c1=NEG_INF, c2=NEG_INF, c3=NEG_INF;
    int   i0=0x7fffffff, i1=0x7fffffff, i2=0x7fffffff, i3=0x7fffffff;
    for (int it = 0; it < iters; it++) {
        int qd = it*32 + lane;
        float4 d4 = make_float4(NEG_INF,NEG_INF,NEG_INF,NEG_INF);
        if (qd < nq) d4 = Dr4[qd];
        float dv[4] = {d4.x, d4.y, d4.z, d4.w};
#pragma unroll
        for (int s = 0; s < 4; s++) {
            float d = dv[s]; int id = qd*4 + s;
            if (d > c3) {
                if (d > c0)      { c3=c2;i3=i2; c2=c1;i2=i1; c1=c0;i1=i0; c0=d;i0=id; }
                else if (d > c1) { c3=c2;i3=i2; c2=c1;i2=i1; c1=d;i1=id; }
                else if (d > c2) { c3=c2;i3=i2; c2=d;i2=id; }
                else             { c3=d;i3=id; }
            }
        }
    }
    float oc3 = c3;
    int b = row / Mq, qc = row - b*Mq;
    int* orow = out + ((size_t)b*Qn + q0 + qc)*KK;

    // extraction: KK warp-argmax rounds over the sorted per-lane lists
    int p = 0;
    float thr = NEG_INF;
    for (int t = 0; t < KK; t++) {
        float v  = (p==0)?c0:(p==1)?c1:(p==2)?c2:(p==3)?c3:NEG_INF;
        int   id = (p==0)?i0:(p==1)?i1:(p==2)?i2:(p==3)?i3:0x7fffffff;
        float mv = v; int mi = id;
#pragma unroll
        for (int off = 16; off; off >>= 1) {
            float ov = __shfl_down_sync(~0u, mv, off);
            int   oi = __shfl_down_sync(~0u, mi, off);
            if (ov > mv || (ov == mv && oi < mi)) { mv = ov; mi = oi; }
        }
        mv = __shfl_sync(~0u, mv, 0);
        mi = __shfl_sync(~0u, mi, 0);
        if (v == mv && id == mi) p++;
        if (lane == 0) orow[t] = mi;
        thr = mv;
    }
    unsigned unsafe = __ballot_sync(~0u, oc3 >= thr);
    if (!unsafe) return;

    // fallback: phase B collect (>= thr is still a valid lower bound) + rank select
    int cnt = 0;
    for (int it = 0; it < iters; it++) {
        int qd = it*32 + lane;
        bool in = qd < nq;
        float4 d4 = make_float4(NEG_INF,NEG_INF,NEG_INF,NEG_INF);
        if (in) d4 = Dr4[qd];
        float dv[4] = {d4.x, d4.y, d4.z, d4.w};
#pragma unroll
        for (int s = 0; s < 4; s++) {
            bool pr = (dv[s] >= thr);
            unsigned m = __ballot_sync(~0u, pr);
            if (pr) {
                int pos = cnt + __popc(m & ((1u << lane) - 1));
                if (pos < CAP) { cv[wp][pos] = dv[s]; ci[wp][pos] = qd*4 + s; }
            }
            cnt += __popc(m);
        }
    }
    __syncwarp();
    if (cnt <= CAP) {
        for (int j = lane; j < cnt; j += 32) {
            float vj = cv[wp][j]; int ij = ci[wp][j];
            int rank = 0;
            for (int l2 = 0; l2 < cnt; l2++) {
                float vl = cv[wp][l2]; int il = ci[wp][l2];
                if (vl > vj || (vl == vj && il < ij)) rank++;
            }
            if (rank < KK) orow[rank] = ij;
        }
    } else {
        // low-register exhaustive fallback: KK repeated warp-argmax passes
        float lastv = POS_INF; int lasti = -1;
        for (int round = 0; round < KK; round++) {
            float bm = NEG_INF; int bmi = 0x7fffffff;
            for (int qd = lane; qd < nq; qd += 32) {
                float4 d4 = Dr4[qd];
                float dv[4] = {d4.x, d4.y, d4.z, d4.w};
#pragma unroll
                for (int s = 0; s < 4; s++) {
                    float v = dv[s]; int id = qd*4 + s;
                    bool ok = (v < lastv) || (v == lastv && id > lasti);
                    if (ok && (v > bm || (v == bm && id < bmi))) { bm = v; bmi = id; }
                }
            }
#pragma unroll
            for (int off = 16; off; off >>= 1) {
                float ov = __shfl_down_sync(~0u, bm, off);
                int oi = __shfl_down_sync(~0u, bmi, off);
                if (ov > bm || (ov == bm && oi < bmi)) { bm = ov; bmi = oi; }
            }
            bm = __shfl_sync(~0u, bm, 0);
            bmi = __shfl_sync(~0u, bmi, 0);
            if (lane == 0) orow[round] = bmi;
            lastv = bm; lasti = bmi;
        }
    }
}

// ------------ generic GEMM ------------
__global__ void __launch_bounds__(256) gemm_kernel(
    const float* __restrict__ W, int ldW, int wofs, int C1, int C2,
    const float* __restrict__ X1, size_t sX1, const int* __restrict__ gidx,
    const float* __restrict__ X2, size_t sX2,
    int N, const float* __restrict__ bias, int Ofull, int act, int redmax, int wdiff,
    float* __restrict__ Y)
{
    __shared__ float Ws[16][65], Xs[16][65];
    __shared__ float sred[16][64];
    int b = blockIdx.z, n0 = blockIdx.x*64, o0 = blockIdx.y*64;
    int tx = threadIdx.x, ty = threadIdx.y, t = ty*16 + tx;
    int Ctot = C1 + C2;
    const int* gb = gidx ? gidx + (size_t)b*N : (const int*)0;
    float acc[4][4] = {};
    for (int kt = 0; kt < Ctot; kt += 16) {
        for (int e = t; e < 1024; e += 256) {
            int ol = e >> 4, cc = e & 15, k = kt + cc;
            float wv = 0.f;
            if (k < Ctot) {
                const float* wr = W + (size_t)(o0+ol)*ldW;
                wv = wdiff ? (wr[Ctot + k] - wr[k]) : wr[wofs + k];
            }
            Ws[cc][ol] = wv;
            int n = n0 + ol;
            float v = 0.f;
            if (k < C1) {
                int r = gb ? gb[n] : n;
                v = X1[(size_t)b*sX1 + (size_t)r*C1 + k];
            } else if (k < Ctot) {
                v = X2[(size_t)b*sX2 + (size_t)n*C2 + (k - C1)];
            }
            Xs[cc][ol] = v;
        }
        __syncthreads();
#pragma unroll
        for (int cc = 0; cc < 16; cc++) {
            float wv[4], xv[4];
#pragma unroll
            for (int j = 0; j < 4; j++) wv[j] = Ws[cc][tx*4+j];
#pragma unroll
            for (int i = 0; i < 4; i++) xv[i] = Xs[cc][ty*4+i];
#pragma unroll
            for (int i = 0; i < 4; i++)
#pragma unroll
                for (int j = 0; j < 4; j++) acc[i][j] = fmaf(wv[j], xv[i], acc[i][j]);
        }
        __syncthreads();
    }
    if (!redmax) {
        float4 vb = make_float4(0.f,0.f,0.f,0.f);
        if (bias) vb = *(const float4*)&bias[(size_t)b*Ofull + o0 + tx*4];
#pragma unroll
        for (int i = 0; i < 4; i++) {
            int n = n0 + ty*4 + i;
            float4 v;
            v.x = acc[i][0] + vb.x; v.y = acc[i][1] + vb.y;
            v.z = acc[i][2] + vb.z; v.w = acc[i][3] + vb.w;
            if (act) { v.x = lrelu(v.x); v.y = lrelu(v.y); v.z = lrelu(v.z); v.w = lrelu(v.w); }
            *(float4*)&Y[((size_t)b*N + n)*Ofull + o0 + tx*4] = v;
        }
    } else {
#pragma unroll
        for (int j = 0; j < 4; j++) {
            float m = NEG_INF;
#pragma unroll
            for (int i = 0; i < 4; i++) m = fmaxf(m, lrelu(acc[i][j]));
            sred[ty][tx*4+j] = m;
        }
        __syncthreads();
        if (t < 64) {
            float mm = NEG_INF;
#pragma unroll
            for (int y = 0; y < 16; y++) mm = fmaxf(mm, sred[y][t]);
            Y[(size_t)((size_t)b*Ofull + o0 + t)*gridDim.x + blockIdx.x] = mm;
        }
    }
}

__global__ void __launch_bounds__(256) redpart_kernel(const float* __restrict__ part, int NB, float* __restrict__ xt){
    int t = blockIdx.x*256 + threadIdx.x;
    if (t < 4096) {
        float m = NEG_INF;
        for (int c = 0; c < NB; c++) m = fmaxf(m, part[(size_t)t*NB + c]);
        xt[t] = m;
    }
}

// ------------ edge conv: warp per point ------------
template <int C, int KK, bool TWO>
__global__ void __launch_bounds__(128) edge_kernel(
    const float* __restrict__ F, const int* __restrict__ idx,
    const float* __restrict__ W0, const float* __restrict__ W1,
    const float* __restrict__ cc, int N, float* __restrict__ out)
{
    __shared__ __align__(16) float sW[64*64];
    __shared__ __align__(16) float sbuf[4*KK*64];
    __shared__ int sidx[4][KK];
    int b = blockIdx.y;
    int wp = threadIdx.x >> 5, lane = threadIdx.x & 31;
    int p = blockIdx.x*4 + wp;
    for (int e = threadIdx.x; e < 64*64; e += 128) {
        int o = e >> 6, i = e & 63;
        if (i < C) sW[i*64 + o] = W0[o*2*C + i];
    }
    if (lane < KK) sidx[wp][lane] = idx[((size_t)b*N + p)*KK + lane];
    __syncthreads();
    float* buf = sbuf + wp*KK*64;
    const float* Fb = F + (size_t)b*N*C;
    if (C == 64) {
        for (int q = lane; q < KK*16; q += 32) {
            int j = q >> 4, i4 = q & 15;
            ((float4*)(buf + j*64))[i4] = ((const float4*)(Fb + (size_t)sidx[wp][j]*64))[i4];
        }
    } else {
        for (int e = lane; e < KK*C; e += 32) {
            int j = e / C, i = e - j*C;
            buf[j*64 + i] = Fb[(size_t)sidx[wp][j]*C + i];
        }
    }
    __syncwarp();
    int o0 = lane, o1 = lane + 32;
    float cc0 = cc[((size_t)b*N + p)*64 + o0];
    float cc1 = cc[((size_t)b*N + p)*64 + o1];
    float aA[KK], aB[KK];
#pragma unroll
    for (int j = 0; j < KK; j++) { aA[j] = cc0; aB[j] = cc1; }
#pragma unroll 4
    for (int i = 0; i < C; i++) {
        float w0 = sW[i*64 + o0], w1 = sW[i*64 + o1];
#pragma unroll
        for (int j = 0; j < KK; j++) {
            float nb = buf[j*64 + i];
            aA[j] = fmaf(w0, nb, aA[j]);
            aB[j] = fmaf(w1, nb, aB[j]);
        }
    }
    if (TWO) {
        __syncwarp();
#pragma unroll
        for (int j = 0; j < KK; j++) {
            buf[j*64 + o0] = lrelu(aA[j]);
            buf[j*64 + o1] = lrelu(aB[j]);
        }
        __syncthreads();
        for (int e = threadIdx.x; e < 64*64; e += 128) {
            int o = e >> 6, i = e & 63;
            sW[i*64 + o] = W1[o*64 + i];
        }
        __syncthreads();
#pragma unroll
        for (int j = 0; j < KK; j++) { aA[j] = 0.f; aB[j] = 0.f; }
#pragma unroll 4
        for (int i = 0; i < 64; i++) {
            float w0 = sW[i*64 + o0], w1 = sW[i*64 + o1];
#pragma unroll
            for (int j = 0; j < KK; j++) {
                float y = buf[j*64 + i];
                aA[j] = fmaf(w0, y, aA[j]);
                aB[j] = fmaf(w1, y, aB[j]);
            }
        }
    }
    float m0 = NEG_INF, m1 = NEG_INF;
#pragma unroll
    for (int j = 0; j < KK; j++) { m0 = fmaxf(m0, lrelu(aA[j])); m1 = fmaxf(m1, lrelu(aB[j])); }
    float* ob = out + ((size_t)b*N + p)*64;
    ob[o0] = m0; ob[o1] = m1;
}

// ------------ gather-max for rand_pool ------------
__global__ void __launch_bounds__(64) gathermax_kernel(const float* __restrict__ F, int Nsrc,
                                                       const int* __restrict__ idx, int M, float* __restrict__ out){
    int b = blockIdx.y, p = blockIdx.x, c = threadIdx.x;
    __shared__ int si[20];
    if (c < 20) si[c] = idx[((size_t)b*M + p)*20 + c];
    __syncthreads();
    float m = NEG_INF;
    for (int j = 0; j < 20; j++) m = fmaxf(m, F[((size_t)b*Nsrc + si[j])*64 + c]);
    out[((size_t)b*M + p)*64 + c] = m;
}

__global__ void gmax_kernel(){
    int t = blockIdx.x*256 + threadIdx.x;
    if (t < 4096) {
        float m = g_xt[t];
        for (int s = 1; s < 4; s++) m = fmaxf(m, g_xt[s*4096 + t]);
        g_gv[t] = m;
    }
}

__global__ void __launch_bounds__(256) bias13_kernel(const float* __restrict__ w13){
    int o = threadIdx.x, b = blockIdx.y;
    const float* g = g_gv + (size_t)b*1024;
    float s = 0.f;
    for (int c = 0; c < 1024; c++) s = fmaf(w13[(size_t)o*1088 + c], g[c], s);
    g_b13[b*256 + o] = s;
}

// out-of-place residual relu
__global__ void resid_kernel(const float* __restrict__ x, const float* __restrict__ f,
                             float* __restrict__ z, int total){
    int t = blockIdx.x*256 + threadIdx.x;
    if (t < total) { float v = x[t] + f[t]; z[t] = v > 0.f ? v : 0.f; }
}

// ------------ 1-NN for unpool ------------
__global__ void __launch_bounds__(128) argmax1_kernel(int Qn, int Rn, int* __restrict__ out){
    __shared__ float sx[1024], sy[1024], sz[1024];
    int wp = threadIdx.x >> 5, lane = threadIdx.x & 31;
    int row0 = blockIdx.x*4;
    int b = row0 / Qn;
    const float* cb = g_coord + (size_t)b*4096*3;
    for (int i = threadIdx.x; i < Rn; i += 128) {
        sx[i] = cb[i*3]; sy[i] = cb[i*3+1]; sz[i] = cb[i*3+2];
    }
    __syncthreads();
    int row = row0 + wp;
    int q = row - b*Qn;
    float qx = cb[q*3], qy = cb[q*3+1], qz = cb[q*3+2];
    float bd = NEG_INF; int bi = 0x7fffffff;
    for (int r = lane; r < Rn; r += 32) {
        float dx = sx[r]-qx, dy = sy[r]-qy, dz = sz[r]-qz;
        float d = -(dx*dx + dy*dy + dz*dz);
        if (d > bd || (d == bd && r < bi)) { bd = d; bi = r; }
    }
    for (int off = 16; off; off >>= 1) {
        float od = __shfl_down_sync(~0u, bd, off);
        int oi = __shfl_down_sync(~0u, bi, off);
        if (od > bd || (od == bd && oi < bi)) { bd = od; bi = oi; }
    }
    if (lane == 0) out[row] = bi;
}

// ------------ final 13x128 conv ------------
__global__ void __launch_bounds__(256) conv17_kernel(const float* __restrict__ H, const float* __restrict__ W,
                                                     float* __restrict__ out){
    __shared__ float sw[13*128];
    int t = threadIdx.x;
    for (int e = t; e < 13*128; e += 256) sw[e] = W[e];
    __syncthreads();
    int n = blockIdx.x*256 + t, b = blockIdx.y;
    const float4* h4 = (const float4*)(H + ((size_t)b*4096 + n)*128);
    float acc[13];
#pragma unroll
    for (int o = 0; o < 13; o++) acc[o] = 0.f;
    for (int i4 = 0; i4 < 32; i4++) {
        float4 hv = h4[i4];
#pragma unroll
        for (int o = 0; o < 13; o++) {
            acc[o] = fmaf(sw[o*128 + i4*4+0], hv.x, acc[o]);
            acc[o] = fmaf(sw[o*128 + i4*4+1], hv.y, acc[o]);
            acc[o] = fmaf(sw[o*128 + i4*4+2], hv.z, acc[o]);
            acc[o] = fmaf(sw[o*128 + i4*4+3], hv.w, acc[o]);
        }
    }
#pragma unroll
    for (int o = 0; o < 13; o++) out[((size_t)b*13 + o)*4096 + n] = acc[o];
}

// ------------ host ------------
static float* dptr(const void* sym){ void* p = 0; cudaGetSymbolAddress(&p, (const void*)sym); return (float*)p; }

extern "C" void kernel_launch(void* const* d_in, const int* in_sizes, int n_in,
                              void* d_out, int out_size) {
    const float* x = (const float*)d_in[0];
    const float* w_ec1_0 = (const float*)d_in[1];
    const float* w_ec1_1 = (const float*)d_in[2];
    const float* w_ec2_0 = (const float*)d_in[3];
    const float* w_ec2_1 = (const float*)d_in[4];
    const float* w_ec4_0 = (const float*)d_in[5];
    const float* w_ec4_1 = (const float*)d_in[6];
    const float* w_ec5_0 = (const float*)d_in[7];
    const float* w_ec5_1 = (const float*)d_in[8];
    const float* w_ec7  = (const float*)d_in[9];
    const float* w_ec8  = (const float*)d_in[10];
    const float* w_ec10 = (const float*)d_in[11];
    const float* w_ec11 = (const float*)d_in[12];
    const float* w_pn3  = (const float*)d_in[13];
    const float* w_pn6  = (const float*)d_in[14];
    const float* w_pn9  = (const float*)d_in[15];
    const float* w_pn12 = (const float*)d_in[16];
    const float* w_pn13 = (const float*)d_in[17];
    const float* w_pn14 = (const float*)d_in[18];
    const float* w_pn15 = (const float*)d_in[19];
    const float* w_pn16 = (const float*)d_in[20];
    const float* w_conv17 = (const float*)d_in[21];
    float* out = (float*)d_out;

    static float *D = 0, *Dp, *xT, *coord, *cc, *h, *x0, *h1, *x1, *x1r, *n1f,
                 *h2, *x2, *x2r, *n2f, *h3, *x3, *x3r, *n3f, *xt, *part, *dec0, *dec1, *b13;
    static int *idx, *idxp1, *idxp2, *idxp3, *uA, *uB, *uC;
    static cudaStream_t s1, s2;
    static cudaEvent_t E0, Eprep, Epools, Ex0, Ex1, Ex2, Ex3, Eb13, Ecc1, Eh, Ecc2;
    if (!D) {
        D = dptr(&g_distm); Dp = dptr(&g_distp); xT = dptr(&g_xT); coord = dptr(&g_coord); cc = dptr(&g_cc);
        h = dptr(&g_h); x0 = dptr(&g_x0); h1 = dptr(&g_h1); x1 = dptr(&g_x1); x1r = dptr(&g_x1r); n1f = dptr(&g_n1f);
        h2 = dptr(&g_h2); x2 = dptr(&g_x2); x2r = dptr(&g_x2r); n2f = dptr(&g_n2f);
        h3 = dptr(&g_h3); x3 = dptr(&g_x3); x3r = dptr(&g_x3r); n3f = dptr(&g_n3f);
        xt = dptr(&g_xt); part = dptr(&g_part);
        dec0 = dptr(&g_dec0); dec1 = dptr(&g_dec1); b13 = dptr(&g_b13);
        idx = (int*)dptr(&g_idx);
        idxp1 = (int*)dptr(&g_idxp1); idxp2 = (int*)dptr(&g_idxp2); idxp3 = (int*)dptr(&g_idxp3);
        uA = (int*)dptr(&g_uidxA); uB = (int*)dptr(&g_uidxB); uC = (int*)dptr(&g_uidxC);
        cudaStreamCreateWithFlags(&s1, cudaStreamNonBlocking);
        cudaStreamCreateWithFlags(&s2, cudaStreamNonBlocking);
        cudaEventCreateWithFlags(&E0, cudaEventDisableTiming);
        cudaEventCreateWithFlags(&Eprep, cudaEventDisableTiming);
        cudaEventCreateWithFlags(&Epools, cudaEventDisableTiming);
        cudaEventCreateWithFlags(&Ex0, cudaEventDisableTiming);
        cudaEventCreateWithFlags(&Ex1, cudaEventDisableTiming);
        cudaEventCreateWithFlags(&Ex2, cudaEventDisableTiming);
        cudaEventCreateWithFlags(&Ex3, cudaEventDisableTiming);
        cudaEventCreateWithFlags(&Eb13, cudaEventDisableTiming);
        cudaEventCreateWithFlags(&Ecc1, cudaEventDisableTiming);
        cudaEventCreateWithFlags(&Eh, cudaEventDisableTiming);
        cudaEventCreateWithFlags(&Ecc2, cudaEventDisableTiming);
    }
    dim3 t1616(16,16);

    // fork S1
    cudaEventRecord(E0, 0);
    cudaStreamWaitEvent(s1, E0, 0);
    cudaStreamWaitEvent(s2, E0, 0);
    nodes_kernel<<<63, 256, 0, s1>>>(x, out);

    prep_kernel<<<dim3(16,4), 256>>>(x);
    cudaEventRecord(Eprep, 0);

    // S1: all coordinate-only kNN work (pools + unpool argmax)
    cudaStreamWaitEvent(s1, Eprep, 0);
    dist2_kernel<<<dim3(32,8,4), 256, 0, s1>>>(coord, 4096*3, coord, 4096*3, 3, 1024, 0, 4096, Dp);
    topk_kernel<20><<<512, 256, 0, s1>>>(Dp, 1024, 4096, 1024, 0, idxp1);
    dist2_kernel<<<dim3(8,2,4), 256, 0, s1>>>(coord, 4096*3, coord, 4096*3, 3, 256, 0, 1024, Dp);
    topk_kernel<20><<<128, 256, 0, s1>>>(Dp, 256, 1024, 256, 0, idxp2);
    dist_kernel<<<dim3(4,1,4), t1616, 0, s1>>>(coord, 4096*3, coord, 4096*3, 3, 64, 256, Dp);
    topk_kernel<20><<<32, 256, 0, s1>>>(Dp, 64, 256, 64, 0, idxp3);
    argmax1_kernel<<<256, 128, 0, s1>>>(256, 64, uA);
    argmax1_kernel<<<1024, 128, 0, s1>>>(1024, 256, uB);
    argmax1_kernel<<<4096, 128, 0, s1>>>(4096, 1024, uC);
    cudaEventRecord(Epools, s1);

    // S2: cc for ec1 (feature-only, overlaps dist+topk)
    cudaStreamWaitEvent(s2, Eprep, 0);
    gemm_kernel<<<dim3(64,1,4), t1616, 0, s2>>>(w_ec1_0, 18, 0, 9, 0, xT, 4096*9, 0, 0, 0, 4096, 0, 64, 0, 0, 1, cc);
    cudaEventRecord(Ecc1, s2);

    // --- ec1 ---
    dist2_kernel<<<dim3(32,32,4), 256>>>(xT, 4096*9, xT, 4096*9, 9, 4096, 0, 4096, D);
    topk_kernel<20><<<2048, 256>>>(D, 4096, 4096, 4096, 0, idx);
    cudaStreamWaitEvent(0, Ecc1, 0);
    edge_kernel<9,20,true><<<dim3(1024,4), 128>>>(xT, idx, w_ec1_0, w_ec1_1, cc, 4096, h);
    cudaEventRecord(Eh, 0);

    // S2: cc for ec2
    cudaStreamWaitEvent(s2, Eh, 0);
    gemm_kernel<<<dim3(64,1,4), t1616, 0, s2>>>(w_ec2_0, 128, 0, 64, 0, h, 4096*64, 0, 0, 0, 4096, 0, 64, 0, 0, 1, cc);
    cudaEventRecord(Ecc2, s2);

    // --- ec2 ---
    dist2_kernel<<<dim3(32,32,4), 256>>>(h, 4096*64, h, 4096*64, 64, 4096, 0, 4096, D);
    topk_kernel<20><<<2048, 256>>>(D, 4096, 4096, 4096, 0, idx);
    cudaStreamWaitEvent(0, Ecc2, 0);
    edge_kernel<64,20,true><<<dim3(1024,4), 128>>>(h, idx, w_ec2_0, w_ec2_1, cc, 4096, x0);
    cudaEventRecord(Ex0, 0);

    // S1: pn3
    cudaStreamWaitEvent(s1, Ex0, 0);
    gemm_kernel<<<dim3(64,16,4), t1616, 0, s1>>>(w_pn3, 64, 0, 64, 0, x0, 4096*64, 0, 0, 0, 4096, 0, 1024, 1, 1, 0, part);
    redpart_kernel<<<16, 256, 0, s1>>>(part, 64, xt);

    // --- pool1 + ec4/ec5 ---
    cudaStreamWaitEvent(0, Epools, 0);
    gathermax_kernel<<<dim3(1024,4), 64>>>(x0, 4096, idxp1, 1024, n1f);
    dist2_kernel<<<dim3(8,8,4), 256>>>(n1f, 1024*64, n1f, 1024*64, 64, 1024, 0, 1024, D);
    topk_kernel<20><<<512, 256>>>(D, 1024, 1024, 1024, 0, idx);
    gemm_kernel<<<dim3(16,1,4), t1616>>>(w_ec4_0, 128, 0, 64, 0, n1f, 1024*64, 0, 0, 0, 1024, 0, 64, 0, 0, 1, cc);
    edge_kernel<64,20,true><<<dim3(256,4), 128>>>(n1f, idx, w_ec4_0, w_ec4_1, cc, 1024, h1);
    dist2_kernel<<<dim3(8,8,4), 256>>>(h1, 1024*64, h1, 1024*64, 64, 1024, 0, 1024, D);
    topk_kernel<20><<<512, 256>>>(D, 1024, 1024, 1024, 0, idx);
    gemm_kernel<<<dim3(16,1,4), t1616>>>(w_ec5_0, 128, 0, 64, 0, h1, 1024*64, 0, 0, 0, 1024, 0, 64, 0, 0, 1, cc);
    edge_kernel<64,20,true><<<dim3(256,4), 128>>>(h1, idx, w_ec5_0, w_ec5_1, cc, 1024, x1);
    cudaEventRecord(Ex1, 0);

    // S1: pn6
    cudaStreamWaitEvent(s1, Ex1, 0);
    gemm_kernel<<<dim3(16,16,4), t1616, 0, s1>>>(w_pn6, 64, 0, 64, 0, x1, 1024*64, 0, 0, 0, 1024, 0, 1024, 1, 1, 0, part);
    redpart_kernel<<<16, 256, 0, s1>>>(part, 16, xt + 4096);

    // --- resid1 + pool2 + ec7/ec8 ---
    resid_kernel<<<1024, 256>>>(x1, n1f, x1r, 4*1024*64);
    gathermax_kernel<<<dim3(256,4), 64>>>(x1r, 1024, idxp2, 256, n2f);
    dist2_kernel<<<dim3(2,2,4), 256>>>(n2f, 256*64, n2f, 256*64, 64, 256, 0, 256, D);
    topk_kernel<20><<<128, 256>>>(D, 256, 256, 256, 0, idx);
    gemm_kernel<<<dim3(4,1,4), t1616>>>(w_ec7, 128, 0, 64, 0, n2f, 256*64, 0, 0, 0, 256, 0, 64, 0, 0, 1, cc);
    edge_kernel<64,20,false><<<dim3(64,4), 128>>>(n2f, idx, w_ec7, 0, cc, 256, h2);
    dist2_kernel<<<dim3(2,2,4), 256>>>(h2, 256*64, h2, 256*64, 64, 256, 0, 256, D);
    topk_kernel<20><<<128, 256>>>(D, 256, 256, 256, 0, idx);
    gemm_kernel<<<dim3(4,1,4), t1616>>>(w_ec8, 128, 0, 64, 0, h2, 256*64, 0, 0, 0, 256, 0, 64, 0, 0, 1, cc);
    edge_kernel<64,20,false><<<dim3(64,4), 128>>>(h2, idx, w_ec8, 0, cc, 256, x2);
    cudaEventRecord(Ex2, 0);

    // S1: pn9
    cudaStreamWaitEvent(s1, Ex2, 0);
    gemm_kernel<<<dim3(4,16,4), t1616, 0, s1>>>(w_pn9, 64, 0, 64, 0, x2, 256*64, 0, 0, 0, 256, 0, 1024, 1, 1, 0, part);
    redpart_kernel<<<16, 256, 0, s1>>>(part, 4, xt + 8192);

    // --- resid2 + pool3 + ec10/ec11 ---
    resid_kernel<<<256, 256>>>(x2, n2f, x2r, 4*256*64);
    gathermax_kernel<<<dim3(64,4), 64>>>(x2r, 256, idxp3, 64, n3f);
    dist_kernel<<<dim3(1,1,4), t1616>>>(n3f, 64*64, n3f, 64*64, 64, 64, 64, D);
    topk_kernel<10><<<32, 256>>>(D, 64, 64, 64, 0, idx);
    gemm_kernel<<<dim3(1,1,4), t1616>>>(w_ec10, 128, 0, 64, 0, n3f, 64*64, 0, 0, 0, 64, 0, 64, 0, 0, 1, cc);
    edge_kernel<64,10,false><<<dim3(16,4), 128>>>(n3f, idx, w_ec10, 0, cc, 64, h3);
    dist_kernel<<<dim3(1,1,4), t1616>>>(h3, 64*64, h3, 64*64, 64, 64, 64, D);
    topk_kernel<10><<<32, 256>>>(D, 64, 64, 64, 0, idx);
    gemm_kernel<<<dim3(1,1,4), t1616>>>(w_ec11, 128, 0, 64, 0, h3, 64*64, 0, 0, 0, 64, 0, 64, 0, 0, 1, cc);
    edge_kernel<64,10,false><<<dim3(16,4), 128>>>(h3, idx, w_ec11, 0, cc, 64, x3);
    cudaEventRecord(Ex3, 0);

    // S1: pn12 + global feature
    cudaStreamWaitEvent(s1, Ex3, 0);
    gemm_kernel<<<dim3(1,16,4), t1616, 0, s1>>>(w_pn12, 64, 0, 64, 0, x3, 64*64, 0, 0, 0, 64, 0, 1024, 1, 1, 0, part);
    redpart_kernel<<<16, 256, 0, s1>>>(part, 1, xt + 12288);
    gmax_kernel<<<16, 256, 0, s1>>>();
    bias13_kernel<<<dim3(1,4), 256, 0, s1>>>(w_pn13);
    cudaEventRecord(Eb13, s1);

    // --- resid3 + decoder ---
    resid_kernel<<<64, 256>>>(x3, n3f, x3r, 4*64*64);
    cudaStreamWaitEvent(0, Eb13, 0);
    gemm_kernel<<<dim3(1,4,4), t1616>>>(w_pn13, 1088, 1024, 64, 0, x3r, 64*64, 0, 0, 0, 64,
                                        b13, 256, 1, 0, 0, dec0);
    gemm_kernel<<<dim3(4,4,4), t1616>>>(w_pn14, 320, 0, 256, 64, dec0, 64*256, uA, x2r, 256*64,
                                        256, 0, 256, 1, 0, 0, dec1);
    gemm_kernel<<<dim3(16,4,4), t1616>>>(w_pn15, 320, 0, 256, 64, dec1, 256*256, uB, x1r, 1024*64,
                                         1024, 0, 256, 1, 0, 0, dec0);
    gemm_kernel<<<dim3(64,2,4), t1616>>>(w_pn16, 320, 0, 256, 64, dec0, 1024*256, uC, x0, 4096*64,
                                         4096, 0, 128, 1, 0, 0, dec1);
    conv17_kernel<<<dim3(16,4), 256>>>(dec1, w_conv17, out);
}

// round 16
// speedup vs baseline: 1.0272x; 1.0272x over previous
#include <cuda_runtime.h>

#define NEG_INF -3.402823466e38f
#define POS_INF 3.402823466e38f

// ------------ device scratch ------------
__device__ float g_distm[4UL*4096*4096];
__device__ float g_distp[4UL*1024*4096];
__device__ float g_xT[4*4096*9];
__device__ float g_coord[4*4096*3];
__device__ int   g_idx[4*4096*20];
__device__ int   g_idxp1[4*1024*20];
__device__ int   g_idxp2[4*256*20];
__device__ int   g_idxp3[4*64*20];
__device__ float g_cc[4*4096*64];
__device__ float g_h[4*4096*64];
__device__ float g_x0[4*4096*64];
__device__ float g_h1[4*1024*64];
__device__ float g_x1[4*1024*64];
__device__ float g_x1r[4*1024*64];
__device__ float g_n1f[4*1024*64];
__device__ float g_h2[4*256*64];
__device__ float g_x2[4*256*64];
__device__ float g_x2r[4*256*64];
__device__ float g_n2f[4*256*64];
__device__ float g_h3[4*64*64];
__device__ float g_x3[4*64*64];
__device__ float g_x3r[4*64*64];
__device__ float g_n3f[4*64*64];
__device__ float g_xt[4*4*1024];
__device__ float g_gv[4*1024];
__device__ float g_b13[4*256];
__device__ float g_part[4*1024*64];
__device__ float g_dec0[4UL*4096*256];
__device__ float g_dec1[4UL*4096*256];
__device__ int   g_uidxA[4*256];
__device__ int   g_uidxB[4*1024];
__device__ int   g_uidxC[4*4096];

__device__ __forceinline__ float lrelu(float v){ return v > 0.f ? v : 0.2f*v; }

// ------------ prep: transpose x, coords ------------
__global__ void __launch_bounds__(256) prep_kernel(const float* __restrict__ x){
    int n = blockIdx.x*256 + threadIdx.x, b = blockIdx.y;
    if (n >= 4096) return;
    const float* xb = x + (size_t)b*9*4096;
    float v[9];
#pragma unroll
    for (int c = 0; c < 9; c++) v[c] = xb[(size_t)c*4096 + n];
    float* r = g_xT + ((size_t)b*4096 + n)*9;
#pragma unroll
    for (int c = 0; c < 9; c++) r[c] = v[c];
    float* cr = g_coord + ((size_t)b*4096 + n)*3;
    cr[0]=v[0]; cr[1]=v[1]; cr[2]=v[2];
}

// node1/2/3 outputs (slices of x)
__global__ void __launch_bounds__(256) nodes_kernel(const float* __restrict__ x, float* __restrict__ o){
    int t = blockIdx.x*256 + threadIdx.x;
    const int T1 = 4*3*1024, T2 = 4*3*256, T3 = 4*3*64;
    if (t < T1) {
        int n = t & 1023, c = (t>>10)%3, b = t/(3*1024);
        o[212992 + t] = x[((size_t)b*9 + c)*4096 + n];
    } else if (t < T1+T2) {
        int u = t-T1; int n = u & 255, c = (u>>8)%3, b = u/(3*256);
        o[212992 + T1 + u] = x[((size_t)b*9 + c)*4096 + n];
    } else if (t < T1+T2+T3) {
        int u = t-T1-T2; int n = u & 63, c = (u>>6)%3, b = u/(3*64);
        o[212992 + T1 + T2 + u] = x[((size_t)b*9 + c)*4096 + n];
    }
}

// ------------ neg dist score 64x64 tile: v = 2<q,r> - |r|^2 ------------
__global__ void __launch_bounds__(256) dist_kernel(
    const float* __restrict__ Q, size_t sQ, const float* __restrict__ R, size_t sR,
    int C, int Qn, int Nr, float* __restrict__ D)
{
    __shared__ float Qs[16][65], Rs[16][65];
    __shared__ float srn[64];
    int b = blockIdx.z, q0 = blockIdx.y*64, r0 = blockIdx.x*64;
    int tx = threadIdx.x, ty = threadIdx.y, t = ty*16 + tx;
    const float* Qb = Q + (size_t)b*sQ;
    const float* Rb = R + (size_t)b*sR;
    float acc[4][4] = {};
    float rnacc = 0.f;
    for (int kt = 0; kt < C; kt += 16) {
        for (int e = t; e < 1024; e += 256) {
            int pl = e >> 4, cc = e & 15, k = kt + cc;
            Qs[cc][pl] = (k < C) ? Qb[(size_t)(q0+pl)*C + k] : 0.f;
            Rs[cc][pl] = (k < C) ? Rb[(size_t)(r0+pl)*C + k] : 0.f;
        }
        __syncthreads();
        if (t < 64) {
#pragma unroll
            for (int cc = 0; cc < 16; cc++) { float v = Rs[cc][t]; rnacc = fmaf(v, v, rnacc); }
        }
#pragma unroll
        for (int cc = 0; cc < 16; cc++) {
            float qv[4], rv[4];
#pragma unroll
            for (int i = 0; i < 4; i++) qv[i] = Qs[cc][ty*4+i];
#pragma unroll
            for (int j = 0; j < 4; j++) rv[j] = Rs[cc][tx*4+j];
#pragma unroll
            for (int i = 0; i < 4; i++)
#pragma unroll
                for (int j = 0; j < 4; j++) acc[i][j] = fmaf(qv[i], rv[j], acc[i][j]);
        }
        __syncthreads();
    }
    if (t < 64) srn[t] = rnacc;
    __syncthreads();
    float4 rn4;
    rn4.x = srn[tx*4]; rn4.y = srn[tx*4+1]; rn4.z = srn[tx*4+2]; rn4.w = srn[tx*4+3];
#pragma unroll
    for (int i = 0; i < 4; i++) {
        int q = q0 + ty*4 + i;
        float4 v;
        v.x = 2.f*acc[i][0] - rn4.x;
        v.y = 2.f*acc[i][1] - rn4.y;
        v.z = 2.f*acc[i][2] - rn4.z;
        v.w = 2.f*acc[i][3] - rn4.w;
        *(float4*)&D[((size_t)b*Qn + q)*Nr + r0 + tx*4] = v;
    }
}

// ------------ neg dist score 128x128 tile / 8x8 ------------
__global__ void __launch_bounds__(256) dist2_kernel(
    const float* __restrict__ Q, size_t sQ, const float* __restrict__ R, size_t sR,
    int C, int QnD, int q0, int Nr, float* __restrict__ D)
{
    __shared__ float Qs[16][132], Rs[16][132];
    __shared__ float srn[128];
    int b = blockIdx.z, qb = blockIdx.y*128, r0 = blockIdx.x*128;
    int t = threadIdx.x;
    int tx = t & 15, ty = t >> 4;
    const float* Qb = Q + (size_t)b*sQ;
    const float* Rb = R + (size_t)b*sR;
    float acc[8][8] = {};
    float rnacc = 0.f;
    for (int kt = 0; kt < C; kt += 16) {
        for (int e = t; e < 2048; e += 256) {
            int row = e >> 4, c = e & 15; int k = kt + c;
            Qs[c][row] = (k < C) ? Qb[(size_t)(q0+qb+row)*C + k] : 0.f;
            Rs[c][row] = (k < C) ? Rb[(size_t)(r0+row)*C + k] : 0.f;
        }
        __syncthreads();
        if (t < 128) {
#pragma unroll
            for (int c = 0; c < 16; c++) { float v = Rs[c][t]; rnacc = fmaf(v, v, rnacc); }
        }
#pragma unroll
        for (int c = 0; c < 16; c++) {
            float qv[8], rv[8];
#pragma unroll
            for (int i = 0; i < 8; i++) qv[i] = Qs[c][ty*8+i];
#pragma unroll
            for (int j = 0; j < 8; j++) rv[j] = Rs[c][tx*8+j];
#pragma unroll
            for (int i = 0; i < 8; i++)
#pragma unroll
                for (int j = 0; j < 8; j++) acc[i][j] = fmaf(qv[i], rv[j], acc[i][j]);
        }
        __syncthreads();
    }
    if (t < 128) srn[t] = rnacc;
    __syncthreads();
    float rn8[8];
#pragma unroll
    for (int j = 0; j < 8; j++) rn8[j] = srn[tx*8 + j];
#pragma unroll
    for (int i = 0; i < 8; i++) {
        int qr = qb + ty*8 + i;
        float4 v0, v1;
        v0.x = 2.f*acc[i][0] - rn8[0];
        v0.y = 2.f*acc[i][1] - rn8[1];
        v0.z = 2.f*acc[i][2] - rn8[2];
        v0.w = 2.f*acc[i][3] - rn8[3];
        v1.x = 2.f*acc[i][4] - rn8[4];
        v1.y = 2.f*acc[i][5] - rn8[5];
        v1.z = 2.f*acc[i][6] - rn8[6];
        v1.w = 2.f*acc[i][7] - rn8[7];
        float* dr = &D[((size_t)b*QnD + qr)*Nr + r0 + tx*8];
        *(float4*)dr = v0;
        *(float4*)(dr + 4) = v1;
    }
}

// ------------ top-k per row: two-phase threshold select (R14-proven version) ------------
template <int KK>
__global__ void __launch_bounds__(256) topk_kernel(const float* __restrict__ D, int Mq, int Nr,
                                                   int Qn, int q0, int* __restrict__ out)
{
    const int CAP = 320;
    __shared__ float cv[8][CAP];
    __shared__ int   ci[8][CAP];
    int wp = threadIdx.x >> 5, lane = threadIdx.x & 31;
    int row = blockIdx.x*8 + wp;
    const float4* Dr4 = (const float4*)(D + (size_t)row*Nr);
    int nq = Nr >> 2;
    int iters = (nq + 31) >> 5;

    // phase A: per-lane top-4
    float c0=NEG_INF, c1=NEG_INF, c2=NEG_INF, c3=NEG_INF;
    for (int it = 0; it < iters; it++) {
        int qd = it*32 + lane;
        float4 d4 = make_float4(NEG_INF,NEG_INF,NEG_INF,NEG_INF);
        if (qd < nq) d4 = Dr4[qd];
        float dv[4] = {d4.x, d4.y, d4.z, d4.w};
#pragma unroll
        for (int s = 0; s < 4; s++) {
            float d = dv[s];
            if (d > c3) {
                if (d > c0)      { c3=c2; c2=c1; c1=c0; c0=d; }
                else if (d > c1) { c3=c2; c2=c1; c1=d; }
                else if (d > c2) { c3=c2; c2=d; }
                else             { c3=d; }
            }
        }
    }
    // KK warp-argmax rounds -> thr (<= true KK-th of row)
    float thr = NEG_INF;
    for (int t = 0; t < KK; t++) {
        float mm = fmaxf(fmaxf(c0,c1), fmaxf(c2,c3));
        float wm = mm;
#pragma unroll
        for (int off = 16; off; off >>= 1) wm = fmaxf(wm, __shfl_xor_sync(~0u, wm, off));
        unsigned msk = __ballot_sync(~0u, mm == wm);
        int leader = __ffs(msk) - 1;
        if (lane == leader) {
            if (c0 == wm) c0 = NEG_INF;
            else if (c1 == wm) c1 = NEG_INF;
            else if (c2 == wm) c2 = NEG_INF;
            else c3 = NEG_INF;
        }
        thr = wm;
    }
    // phase B: collect all values >= thr
    int cnt = 0;
    for (int it = 0; it < iters; it++) {
        int qd = it*32 + lane;
        bool in = qd < nq;
        float4 d4 = make_float4(NEG_INF,NEG_INF,NEG_INF,NEG_INF);
        if (in) d4 = Dr4[qd];
        float dv[4] = {d4.x, d4.y, d4.z, d4.w};
#pragma unroll
        for (int s = 0; s < 4; s++) {
            bool p = (dv[s] >= thr);
            unsigned m = __ballot_sync(~0u, p);
            if (p) {
                int pos = cnt + __popc(m & ((1u << lane) - 1));
                if (pos < CAP) { cv[wp][pos] = dv[s]; ci[wp][pos] = qd*4 + s; }
            }
            cnt += __popc(m);
        }
    }
    __syncwarp();
    int b = row / Mq, qc = row - b*Mq;
    int* orow = out + ((size_t)b*Qn + q0 + qc)*KK;
    if (cnt <= CAP) {
        // rank select (v desc, idx asc)
        for (int j = lane; j < cnt; j += 32) {
            float vj = cv[wp][j]; int ij = ci[wp][j];
            int rank = 0;
            for (int l2 = 0; l2 < cnt; l2++) {
                float vl = cv[wp][l2]; int il = ci[wp][l2];
                if (vl > vj || (vl == vj && il < ij)) rank++;
            }
            if (rank < KK) orow[rank] = ij;
        }
    } else {
        // low-register fallback (practically never taken): KK repeated warp-argmax
        float lastv = POS_INF; int lasti = -1;
        for (int round = 0; round < KK; round++) {
            float bm = NEG_INF; int bmi = 0x7fffffff;
            for (int qd = lane; qd < nq; qd += 32) {
                float4 d4 = Dr4[qd];
                float dv[4] = {d4.x, d4.y, d4.z, d4.w};
#pragma unroll
                for (int s = 0; s < 4; s++) {
                    float v = dv[s]; int id = qd*4 + s;
                    bool ok = (v < lastv) || (v == lastv && id > lasti);
                    if (ok && (v > bm || (v == bm && id < bmi))) { bm = v; bmi = id; }
                }
            }
#pragma unroll
            for (int off = 16; off; off >>= 1) {
                float ov = __shfl_down_sync(~0u, bm, off);
                int oi = __shfl_down_sync(~0u, bmi, off);
                if (ov > bm || (ov == bm && oi < bmi)) { bm = ov; bmi = oi; }
            }
            bm = __shfl_sync(~0u, bm, 0);
            bmi = __shfl_sync(~0u, bmi, 0);
            if (lane == 0) orow[round] = bmi;
            lastv = bm; lasti = bmi;
        }
    }
}

// ------------ generic GEMM ------------
__global__ void __launch_bounds__(256) gemm_kernel(
    const float* __restrict__ W, int ldW, int wofs, int C1, int C2,
    const float* __restrict__ X1, size_t sX1, const int* __restrict__ gidx,
    const float* __restrict__ X2, size_t sX2,
    int N, const float* __restrict__ bias, int Ofull, int act, int redmax, int wdiff,
    float* __restrict__ Y)
{
    __shared__ float Ws[16][65], Xs[16][65];
    __shared__ float sred[16][64];
    int b = blockIdx.z, n0 = blockIdx.x*64, o0 = blockIdx.y*64;
    int tx = threadIdx.x, ty = threadIdx.y, t = ty*16 + tx;
    int Ctot = C1 + C2;
    const int* gb = gidx ? gidx + (size_t)b*N : (const int*)0;
    float acc[4][4] = {};
    for (int kt = 0; kt < Ctot; kt += 16) {
        for (int e = t; e < 1024; e += 256) {
            int ol = e >> 4, cc = e & 15, k = kt + cc;
            float wv = 0.f;
            if (k < Ctot) {
                const float* wr = W + (size_t)(o0+ol)*ldW;
                wv = wdiff ? (wr[Ctot + k] - wr[k]) : wr[wofs + k];
            }
            Ws[cc][ol] = wv;
            int n = n0 + ol;
            float v = 0.f;
            if (k < C1) {
                int r = gb ? gb[n] : n;
                v = X1[(size_t)b*sX1 + (size_t)r*C1 + k];
            } else if (k < Ctot) {
                v = X2[(size_t)b*sX2 + (size_t)n*C2 + (k - C1)];
            }
            Xs[cc][ol] = v;
        }
        __syncthreads();
#pragma unroll
        for (int cc = 0; cc < 16; cc++) {
            float wv[4], xv[4];
#pragma unroll
            for (int j = 0; j < 4; j++) wv[j] = Ws[cc][tx*4+j];
#pragma unroll
            for (int i = 0; i < 4; i++) xv[i] = Xs[cc][ty*4+i];
#pragma unroll
            for (int i = 0; i < 4; i++)
#pragma unroll
                for (int j = 0; j < 4; j++) acc[i][j] = fmaf(wv[j], xv[i], acc[i][j]);
        }
        __syncthreads();
    }
    if (!redmax) {
        float4 vb = make_float4(0.f,0.f,0.f,0.f);
        if (bias) vb = *(const float4*)&bias[(size_t)b*Ofull + o0 + tx*4];
#pragma unroll
        for (int i = 0; i < 4; i++) {
            int n = n0 + ty*4 + i;
            float4 v;
            v.x = acc[i][0] + vb.x; v.y = acc[i][1] + vb.y;
            v.z = acc[i][2] + vb.z; v.w = acc[i][3] + vb.w;
            if (act) { v.x = lrelu(v.x); v.y = lrelu(v.y); v.z = lrelu(v.z); v.w = lrelu(v.w); }
            *(float4*)&Y[((size_t)b*N + n)*Ofull + o0 + tx*4] = v;
        }
    } else {
#pragma unroll
        for (int j = 0; j < 4; j++) {
            float m = NEG_INF;
#pragma unroll
            for (int i = 0; i < 4; i++) m = fmaxf(m, lrelu(acc[i][j]));
            sred[ty][tx*4+j] = m;
        }
        __syncthreads();
        if (t < 64) {
            float mm = NEG_INF;
#pragma unroll
            for (int y = 0; y < 16; y++) mm = fmaxf(mm, sred[y][t]);
            Y[(size_t)((size_t)b*Ofull + o0 + t)*gridDim.x + blockIdx.x] = mm;
        }
    }
}

__global__ void __launch_bounds__(256) redpart_kernel(const float* __restrict__ part, int NB, float* __restrict__ xt){
    int t = blockIdx.x*256 + threadIdx.x;
    if (t < 4096) {
        float m = NEG_INF;
        for (int c = 0; c < NB; c++) m = fmaxf(m, part[(size_t)t*NB + c]);
        xt[t] = m;
    }
}

// ------------ edge conv: warp per point ------------
template <int C, int KK, bool TWO>
__global__ void __launch_bounds__(128) edge_kernel(
    const float* __restrict__ F, const int* __restrict__ idx,
    const float* __restrict__ W0, const float* __restrict__ W1,
    const float* __restrict__ cc, int N, float* __restrict__ out)
{
    __shared__ __align__(16) float sW[64*64];
    __shared__ __align__(16) float sbuf[4*KK*64];
    __shared__ int sidx[4][KK];
    int b = blockIdx.y;
    int wp = threadIdx.x >> 5, lane = threadIdx.x & 31;
    int p = blockIdx.x*4 + wp;
    for (int e = threadIdx.x; e < 64*64; e += 128) {
        int o = e >> 6, i = e & 63;
        if (i < C) sW[i*64 + o] = W0[o*2*C + i];
    }
    if (lane < KK) sidx[wp][lane] = idx[((size_t)b*N + p)*KK + lane];
    __syncthreads();
    float* buf = sbuf + wp*KK*64;
    const float* Fb = F + (size_t)b*N*C;
    if (C == 64) {
        for (int q = lane; q < KK*16; q += 32) {
            int j = q >> 4, i4 = q & 15;
            ((float4*)(buf + j*64))[i4] = ((const float4*)(Fb + (size_t)sidx[wp][j]*64))[i4];
        }
    } else {
        for (int e = lane; e < KK*C; e += 32) {
            int j = e / C, i = e - j*C;
            buf[j*64 + i] = Fb[(size_t)sidx[wp][j]*C + i];
        }
    }
    __syncwarp();
    int o0 = lane, o1 = lane + 32;
    float cc0 = cc[((size_t)b*N + p)*64 + o0];
    float cc1 = cc[((size_t)b*N + p)*64 + o1];
    float aA[KK], aB[KK];
#pragma unroll
    for (int j = 0; j < KK; j++) { aA[j] = cc0; aB[j] = cc1; }
#pragma unroll 4
    for (int i = 0; i < C; i++) {
        float w0 = sW[i*64 + o0], w1 = sW[i*64 + o1];
#pragma unroll
        for (int j = 0; j < KK; j++) {
            float nb = buf[j*64 + i];
            aA[j] = fmaf(w0, nb, aA[j]);
            aB[j] = fmaf(w1, nb, aB[j]);
        }
    }
    if (TWO) {
        __syncwarp();
#pragma unroll
        for (int j = 0; j < KK; j++) {
            buf[j*64 + o0] = lrelu(aA[j]);
            buf[j*64 + o1] = lrelu(aB[j]);
        }
        __syncthreads();
        for (int e = threadIdx.x; e < 64*64; e += 128) {
            int o = e >> 6, i = e & 63;
            sW[i*64 + o] = W1[o*64 + i];
        }
        __syncthreads();
#pragma unroll
        for (int j = 0; j < KK; j++) { aA[j] = 0.f; aB[j] = 0.f; }
#pragma unroll 4
        for (int i = 0; i < 64; i++) {
            float w0 = sW[i*64 + o0], w1 = sW[i*64 + o1];
#pragma unroll
            for (int j = 0; j < KK; j++) {
                float y = buf[j*64 + i];
                aA[j] = fmaf(w0, y, aA[j]);
                aB[j] = fmaf(w1, y, aB[j]);
            }
        }
    }
    float m0 = NEG_INF, m1 = NEG_INF;
#pragma unroll
    for (int j = 0; j < KK; j++) { m0 = fmaxf(m0, lrelu(aA[j])); m1 = fmaxf(m1, lrelu(aB[j])); }
    float* ob = out + ((size_t)b*N + p)*64;
    ob[o0] = m0; ob[o1] = m1;
}

// ------------ gather-max for rand_pool ------------
__global__ void __launch_bounds__(64) gathermax_kernel(const float* __restrict__ F, int Nsrc,
                                                       const int* __restrict__ idx, int M, float* __restrict__ out){
    int b = blockIdx.y, p = blockIdx.x, c = threadIdx.x;
    __shared__ int si[20];
    if (c < 20) si[c] = idx[((size_t)b*M + p)*20 + c];
    __syncthreads();
    float m = NEG_INF;
    for (int j = 0; j < 20; j++) m = fmaxf(m, F[((size_t)b*Nsrc + si[j])*64 + c]);
    out[((size_t)b*M + p)*64 + c] = m;
}

__global__ void gmax_kernel(){
    int t = blockIdx.x*256 + threadIdx.x;
    if (t < 4096) {
        float m = g_xt[t];
        for (int s = 1; s < 4; s++) m = fmaxf(m, g_xt[s*4096 + t]);
        g_gv[t] = m;
    }
}

__global__ void __launch_bounds__(256) bias13_kernel(const float* __restrict__ w13){
    int o = threadIdx.x, b = blockIdx.y;
    const float* g = g_gv + (size_t)b*1024;
    float s = 0.f;
    for (int c = 0; c < 1024; c++) s = fmaf(w13[(size_t)o*1088 + c], g[c], s);
    g_b13[b*256 + o] = s;
}

// out-of-place residual relu
__global__ void resid_kernel(const float* __restrict__ x, const float* __restrict__ f,
                             float* __restrict__ z, int total){
    int t = blockIdx.x*256 + threadIdx.x;
    if (t < total) { float v = x[t] + f[t]; z[t] = v > 0.f ? v : 0.f; }
}

// ------------ 1-NN for unpool ------------
__global__ void __launch_bounds__(128) argmax1_kernel(int Qn, int Rn, int* __restrict__ out){
    __shared__ float sx[1024], sy[1024], sz[1024];
    int wp = threadIdx.x >> 5, lane = threadIdx.x & 31;
    int row0 = blockIdx.x*4;
    int b = row0 / Qn;
    const float* cb = g_coord + (size_t)b*4096*3;
    for (int i = threadIdx.x; i < Rn; i += 128) {
        sx[i] = cb[i*3]; sy[i] = cb[i*3+1]; sz[i] = cb[i*3+2];
    }
    __syncthreads();
    int row = row0 + wp;
    int q = row - b*Qn;
    float qx = cb[q*3], qy = cb[q*3+1], qz = cb[q*3+2];
    float bd = NEG_INF; int bi = 0x7fffffff;
    for (int r = lane; r < Rn; r += 32) {
        float dx = sx[r]-qx, dy = sy[r]-qy, dz = sz[r]-qz;
        float d = -(dx*dx + dy*dy + dz*dz);
        if (d > bd || (d == bd && r < bi)) { bd = d; bi = r; }
    }
    for (int off = 16; off; off >>= 1) {
        float od = __shfl_down_sync(~0u, bd, off);
        int oi = __shfl_down_sync(~0u, bi, off);
        if (od > bd || (od == bd && oi < bi)) { bd = od; bi = oi; }
    }
    if (lane == 0) out[row] = bi;
}

// ------------ final 13x128 conv ------------
__global__ void __launch_bounds__(256) conv17_kernel(const float* __restrict__ H, const float* __restrict__ W,
                                                     float* __restrict__ out){
    __shared__ float sw[13*128];
    int t = threadIdx.x;
    for (int e = t; e < 13*128; e += 256) sw[e] = W[e];
    __syncthreads();
    int n = blockIdx.x*256 + t, b = blockIdx.y;
    const float4* h4 = (const float4*)(H + ((size_t)b*4096 + n)*128);
    float acc[13];
#pragma unroll
    for (int o = 0; o < 13; o++) acc[o] = 0.f;
    for (int i4 = 0; i4 < 32; i4++) {
        float4 hv = h4[i4];
#pragma unroll
        for (int o = 0; o < 13; o++) {
            acc[o] = fmaf(sw[o*128 + i4*4+0], hv.x, acc[o]);
            acc[o] = fmaf(sw[o*128 + i4*4+1], hv.y, acc[o]);
            acc[o] = fmaf(sw[o*128 + i4*4+2], hv.z, acc[o]);
            acc[o] = fmaf(sw[o*128 + i4*4+3], hv.w, acc[o]);
        }
    }
#pragma unroll
    for (int o = 0; o < 13; o++) out[((size_t)b*13 + o)*4096 + n] = acc[o];
}

// ------------ host ------------
static float* dptr(const void* sym){ void* p = 0; cudaGetSymbolAddress(&p, (const void*)sym); return (float*)p; }

extern "C" void kernel_launch(void* const* d_in, const int* in_sizes, int n_in,
                              void* d_out, int out_size) {
    const float* x = (const float*)d_in[0];
    const float* w_ec1_0 = (const float*)d_in[1];
    const float* w_ec1_1 = (const float*)d_in[2];
    const float* w_ec2_0 = (const float*)d_in[3];
    const float* w_ec2_1 = (const float*)d_in[4];
    const float* w_ec4_0 = (const float*)d_in[5];
    const float* w_ec4_1 = (const float*)d_in[6];
    const float* w_ec5_0 = (const float*)d_in[7];
    const float* w_ec5_1 = (const float*)d_in[8];
    const float* w_ec7  = (const float*)d_in[9];
    const float* w_ec8  = (const float*)d_in[10];
    const float* w_ec10 = (const float*)d_in[11];
    const float* w_ec11 = (const float*)d_in[12];
    const float* w_pn3  = (const float*)d_in[13];
    const float* w_pn6  = (const float*)d_in[14];
    const float* w_pn9  = (const float*)d_in[15];
    const float* w_pn12 = (const float*)d_in[16];
    const float* w_pn13 = (const float*)d_in[17];
    const float* w_pn14 = (const float*)d_in[18];
    const float* w_pn15 = (const float*)d_in[19];
    const float* w_pn16 = (const float*)d_in[20];
    const float* w_conv17 = (const float*)d_in[21];
    float* out = (float*)d_out;

    static float *D = 0, *Dp, *xT, *coord, *cc, *h, *x0, *h1, *x1, *x1r, *n1f,
                 *h2, *x2, *x2r, *n2f, *h3, *x3, *x3r, *n3f, *xt, *part, *dec0, *dec1, *b13;
    static int *idx, *idxp1, *idxp2, *idxp3, *uA, *uB, *uC;
    static cudaStream_t s1, s2;
    static cudaEvent_t E0, Eprep, Epools, Ex0, Ex1, Ex2, Ex3, Eb13, Ecc1, Eh, Ecc2;
    if (!D) {
        D = dptr(&g_distm); Dp = dptr(&g_distp); xT = dptr(&g_xT); coord = dptr(&g_coord); cc = dptr(&g_cc);
        h = dptr(&g_h); x0 = dptr(&g_x0); h1 = dptr(&g_h1); x1 = dptr(&g_x1); x1r = dptr(&g_x1r); n1f = dptr(&g_n1f);
        h2 = dptr(&g_h2); x2 = dptr(&g_x2); x2r = dptr(&g_x2r); n2f = dptr(&g_n2f);
        h3 = dptr(&g_h3); x3 = dptr(&g_x3); x3r = dptr(&g_x3r); n3f = dptr(&g_n3f);
        xt = dptr(&g_xt); part = dptr(&g_part);
        dec0 = dptr(&g_dec0); dec1 = dptr(&g_dec1); b13 = dptr(&g_b13);
        idx = (int*)dptr(&g_idx);
        idxp1 = (int*)dptr(&g_idxp1); idxp2 = (int*)dptr(&g_idxp2); idxp3 = (int*)dptr(&g_idxp3);
        uA = (int*)dptr(&g_uidxA); uB = (int*)dptr(&g_uidxB); uC = (int*)dptr(&g_uidxC);
        cudaStreamCreateWithFlags(&s1, cudaStreamNonBlocking);
        cudaStreamCreateWithFlags(&s2, cudaStreamNonBlocking);
        cudaEventCreateWithFlags(&E0, cudaEventDisableTiming);
        cudaEventCreateWithFlags(&Eprep, cudaEventDisableTiming);
        cudaEventCreateWithFlags(&Epools, cudaEventDisableTiming);
        cudaEventCreateWithFlags(&Ex0, cudaEventDisableTiming);
        cudaEventCreateWithFlags(&Ex1, cudaEventDisableTiming);
        cudaEventCreateWithFlags(&Ex2, cudaEventDisableTiming);
        cudaEventCreateWithFlags(&Ex3, cudaEventDisableTiming);
        cudaEventCreateWithFlags(&Eb13, cudaEventDisableTiming);
        cudaEventCreateWithFlags(&Ecc1, cudaEventDisableTiming);
        cudaEventCreateWithFlags(&Eh, cudaEventDisableTiming);
        cudaEventCreateWithFlags(&Ecc2, cudaEventDisableTiming);
    }
    dim3 t1616(16,16);

    // fork S1/S2
    cudaEventRecord(E0, 0);
    cudaStreamWaitEvent(s1, E0, 0);
    cudaStreamWaitEvent(s2, E0, 0);
    nodes_kernel<<<63, 256, 0, s1>>>(x, out);

    prep_kernel<<<dim3(16,4), 256>>>(x);
    cudaEventRecord(Eprep, 0);

    // S1: all coordinate-only kNN work (pools + unpool argmax)
    cudaStreamWaitEvent(s1, Eprep, 0);
    dist2_kernel<<<dim3(32,8,4), 256, 0, s1>>>(coord, 4096*3, coord, 4096*3, 3, 1024, 0, 4096, Dp);
    topk_kernel<20><<<512, 256, 0, s1>>>(Dp, 1024, 4096, 1024, 0, idxp1);
    dist2_kernel<<<dim3(8,2,4), 256, 0, s1>>>(coord, 4096*3, coord, 4096*3, 3, 256, 0, 1024, Dp);
    topk_kernel<20><<<128, 256, 0, s1>>>(Dp, 256, 1024, 256, 0, idxp2);
    dist_kernel<<<dim3(4,1,4), t1616, 0, s1>>>(coord, 4096*3, coord, 4096*3, 3, 64, 256, Dp);
    topk_kernel<20><<<32, 256, 0, s1>>>(Dp, 64, 256, 64, 0, idxp3);
    argmax1_kernel<<<256, 128, 0, s1>>>(256, 64, uA);
    argmax1_kernel<<<1024, 128, 0, s1>>>(1024, 256, uB);
    argmax1_kernel<<<4096, 128, 0, s1>>>(4096, 1024, uC);
    cudaEventRecord(Epools, s1);

    // S2: cc for ec1 (feature-only, overlaps dist+topk)
    cudaStreamWaitEvent(s2, Eprep, 0);
    gemm_kernel<<<dim3(64,1,4), t1616, 0, s2>>>(w_ec1_0, 18, 0, 9, 0, xT, 4096*9, 0, 0, 0, 4096, 0, 64, 0, 0, 1, cc);
    cudaEventRecord(Ecc1, s2);

    // --- ec1 ---
    dist2_kernel<<<dim3(32,32,4), 256>>>(xT, 4096*9, xT, 4096*9, 9, 4096, 0, 4096, D);
    topk_kernel<20><<<2048, 256>>>(D, 4096, 4096, 4096, 0, idx);
    cudaStreamWaitEvent(0, Ecc1, 0);
    edge_kernel<9,20,true><<<dim3(1024,4), 128>>>(xT, idx, w_ec1_0, w_ec1_1, cc, 4096, h);
    cudaEventRecord(Eh, 0);

    // S2: cc for ec2
    cudaStreamWaitEvent(s2, Eh, 0);
    gemm_kernel<<<dim3(64,1,4), t1616, 0, s2>>>(w_ec2_0, 128, 0, 64, 0, h, 4096*64, 0, 0, 0, 4096, 0, 64, 0, 0, 1, cc);
    cudaEventRecord(Ecc2, s2);

    // --- ec2 ---
    dist2_kernel<<<dim3(32,32,4), 256>>>(h, 4096*64, h, 4096*64, 64, 4096, 0, 4096, D);
    topk_kernel<20><<<2048, 256>>>(D, 4096, 4096, 4096, 0, idx);
    cudaStreamWaitEvent(0, Ecc2, 0);
    edge_kernel<64,20,true><<<dim3(1024,4), 128>>>(h, idx, w_ec2_0, w_ec2_1, cc, 4096, x0);
    cudaEventRecord(Ex0, 0);

    // S1: pn3
    cudaStreamWaitEvent(s1, Ex0, 0);
    gemm_kernel<<<dim3(64,16,4), t1616, 0, s1>>>(w_pn3, 64, 0, 64, 0, x0, 4096*64, 0, 0, 0, 4096, 0, 1024, 1, 1, 0, part);
    redpart_kernel<<<16, 256, 0, s1>>>(part, 64, xt);

    // --- pool1 + ec4/ec5 ---
    cudaStreamWaitEvent(0, Epools, 0);
    gathermax_kernel<<<dim3(1024,4), 64>>>(x0, 4096, idxp1, 1024, n1f);
    dist2_kernel<<<dim3(8,8,4), 256>>>(n1f, 1024*64, n1f, 1024*64, 64, 1024, 0, 1024, D);
    topk_kernel<20><<<512, 256>>>(D, 1024, 1024, 1024, 0, idx);
    gemm_kernel<<<dim3(16,1,4), t1616>>>(w_ec4_0, 128, 0, 64, 0, n1f, 1024*64, 0, 0, 0, 1024, 0, 64, 0, 0, 1, cc);
    edge_kernel<64,20,true><<<dim3(256,4), 128>>>(n1f, idx, w_ec4_0, w_ec4_1, cc, 1024, h1);
    dist2_kernel<<<dim3(8,8,4), 256>>>(h1, 1024*64, h1, 1024*64, 64, 1024, 0, 1024, D);
    topk_kernel<20><<<512, 256>>>(D, 1024, 1024, 1024, 0, idx);
    gemm_kernel<<<dim3(16,1,4), t1616>>>(w_ec5_0, 128, 0, 64, 0, h1, 1024*64, 0, 0, 0, 1024, 0, 64, 0, 0, 1, cc);
    edge_kernel<64,20,true><<<dim3(256,4), 128>>>(h1, idx, w_ec5_0, w_ec5_1, cc, 1024, x1);
    cudaEventRecord(Ex1, 0);

    // S1: pn6
    cudaStreamWaitEvent(s1, Ex1, 0);
    gemm_kernel<<<dim3(16,16,4), t1616, 0, s1>>>(w_pn6, 64, 0, 64, 0, x1, 1024*64, 0, 0, 0, 1024, 0, 1024, 1, 1, 0, part);
    redpart_kernel<<<16, 256, 0, s1>>>(part, 16, xt + 4096);

    // --- resid1 + pool2 + ec7/ec8 ---
    resid_kernel<<<1024, 256>>>(x1, n1f, x1r, 4*1024*64);
    gathermax_kernel<<<dim3(256,4), 64>>>(x1r, 1024, idxp2, 256, n2f);
    dist2_kernel<<<dim3(2,2,4), 256>>>(n2f, 256*64, n2f, 256*64, 64, 256, 0, 256, D);
    topk_kernel<20><<<128, 256>>>(D, 256, 256, 256, 0, idx);
    gemm_kernel<<<dim3(4,1,4), t1616>>>(w_ec7, 128, 0, 64, 0, n2f, 256*64, 0, 0, 0, 256, 0, 64, 0, 0, 1, cc);
    edge_kernel<64,20,false><<<dim3(64,4), 128>>>(n2f, idx, w_ec7, 0, cc, 256, h2);
    dist2_kernel<<<dim3(2,2,4), 256>>>(h2, 256*64, h2, 256*64, 64, 256, 0, 256, D);
    topk_kernel<20><<<128, 256>>>(D, 256, 256, 256, 0, idx);
    gemm_kernel<<<dim3(4,1,4), t1616>>>(w_ec8, 128, 0, 64, 0, h2, 256*64, 0, 0, 0, 256, 0, 64, 0, 0, 1, cc);
    edge_kernel<64,20,false><<<dim3(64,4), 128>>>(h2, idx, w_ec8, 0, cc, 256, x2);
    cudaEventRecord(Ex2, 0);

    // S1: pn9
    cudaStreamWaitEvent(s1, Ex2, 0);
    gemm_kernel<<<dim3(4,16,4), t1616, 0, s1>>>(w_pn9, 64, 0, 64, 0, x2, 256*64, 0, 0, 0, 256, 0, 1024, 1, 1, 0, part);
    redpart_kernel<<<16, 256, 0, s1>>>(part, 4, xt + 8192);

    // --- resid2 + pool3 + ec10/ec11 ---
    resid_kernel<<<256, 256>>>(x2, n2f, x2r, 4*256*64);
    gathermax_kernel<<<dim3(64,4), 64>>>(x2r, 256, idxp3, 64, n3f);
    dist_kernel<<<dim3(1,1,4), t1616>>>(n3f, 64*64, n3f, 64*64, 64, 64, 64, D);
    topk_kernel<10><<<32, 256>>>(D, 64, 64, 64, 0, idx);
    gemm_kernel<<<dim3(1,1,4), t1616>>>(w_ec10, 128, 0, 64, 0, n3f, 64*64, 0, 0, 0, 64, 0, 64, 0, 0, 1, cc);
    edge_kernel<64,10,false><<<dim3(16,4), 128>>>(n3f, idx, w_ec10, 0, cc, 64, h3);
    dist_kernel<<<dim3(1,1,4), t1616>>>(h3, 64*64, h3, 64*64, 64, 64, 64, D);
    topk_kernel<10><<<32, 256>>>(D, 64, 64, 64, 0, idx);
    gemm_kernel<<<dim3(1,1,4), t1616>>>(w_ec11, 128, 0, 64, 0, h3, 64*64, 0, 0, 0, 64, 0, 64, 0, 0, 1, cc);
    edge_kernel<64,10,false><<<dim3(16,4), 128>>>(h3, idx, w_ec11, 0, cc, 64, x3);
    cudaEventRecord(Ex3, 0);

    // S1: pn12 + global feature
    cudaStreamWaitEvent(s1, Ex3, 0);
    gemm_kernel<<<dim3(1,16,4), t1616, 0, s1>>>(w_pn12, 64, 0, 64, 0, x3, 64*64, 0, 0, 0, 64, 0, 1024, 1, 1, 0, part);
    redpart_kernel<<<16, 256, 0, s1>>>(part, 1, xt + 12288);
    gmax_kernel<<<16, 256, 0, s1>>>();
    bias13_kernel<<<dim3(1,4), 256, 0, s1>>>(w_pn13);
    cudaEventRecord(Eb13, s1);

    // --- resid3 + decoder ---
    resid_kernel<<<64, 256>>>(x3, n3f, x3r, 4*64*64);
    cudaStreamWaitEvent(0, Eb13, 0);
    gemm_kernel<<<dim3(1,4,4), t1616>>>(w_pn13, 1088, 1024, 64, 0, x3r, 64*64, 0, 0, 0, 64,
                                        b13, 256, 1, 0, 0, dec0);
    gemm_kernel<<<dim3(4,4,4), t1616>>>(w_pn14, 320, 0, 256, 64, dec0, 64*256, uA, x2r, 256*64,
                                        256, 0, 256, 1, 0, 0, dec1);
    gemm_kernel<<<dim3(16,4,4), t1616>>>(w_pn15, 320, 0, 256, 64, dec1, 256*256, uB, x1r, 1024*64,
                                         1024, 0, 256, 1, 0, 0, dec0);
    gemm_kernel<<<dim3(64,2,4), t1616>>>(w_pn16, 320, 0, 256, 64, dec0, 1024*256, uC, x0, 4096*64,
                                         4096, 0, 128, 1, 0, 0, dec1);
    conv17_kernel<<<dim3(16,4), 256>>>(dec1, w_conv17, out);
}